// round 10
// baseline (speedup 1.0000x reference)
#include <cuda_runtime.h>

// Spalize: out[k][c][h][w] = img[c][h][w] * (mask[h][w] == k), k in [0,50),
// plus the mask appended (as float) if out_size covers it.
//
// R9 base (1 quad/thread, fully coalesced float4, KSPLIT=25, 6656 blocks)
// + single delta: write-through stores (__stwt, STG.WT) on the write-once
// output. Hypothesis: .wt bypasses the L2 dirty-line lifecycle (allocate /
// mark dirty / lazy writeback) that paces the .cs drain, streaming stores
// straight to the DRAM write queue.

#define KCH 50
#define CCH 3
#define KSPLIT 25
#define KCHUNK (KCH / KSPLIT)   // 2

__device__ __forceinline__ int detect_is64(const int* __restrict__ mask) {
    const int lane = threadIdx.x & 31;
    const int w1 = __ldg(&mask[2 * lane + 1]);
    const int w2 = __ldg(&mask[2 * (lane + 32) + 1]);
    const unsigned b = __ballot_sync(0xffffffffu, (w1 | w2) == 0);
    return b == 0xffffffffu;
}

__device__ __forceinline__ void load_mask_quad(const int* __restrict__ mask,
                                               int q, int is64,
                                               int& m0, int& m1, int& m2, int& m3) {
    if (is64) {
        const int base = q * 8;   // 4 int64s; low word at even idx
        m0 = mask[base + 0]; m1 = mask[base + 2];
        m2 = mask[base + 4]; m3 = mask[base + 6];
    } else {
        const int4 mm = reinterpret_cast<const int4*>(mask)[q];
        m0 = mm.x; m1 = mm.y; m2 = mm.z; m3 = mm.w;
    }
}

__device__ __forceinline__ float4 sel4(float4 ic, int m0, int m1, int m2, int m3, int k) {
    float4 v;
    v.x = (m0 == k) ? ic.x : 0.0f;
    v.y = (m1 == k) ? ic.y : 0.0f;
    v.z = (m2 == k) ? ic.z : 0.0f;
    v.w = (m3 == k) ? ic.w : 0.0f;
    return v;
}

__global__ void __launch_bounds__(256) spalize_fused_kernel(
    const float* __restrict__ img,
    const int*   __restrict__ mask,
    float*       __restrict__ out,
    int nq,            // HW/4
    int nblocksQ,      // ceil(nq/256)
    int nSpalBlocks)   // nblocksQ * KSPLIT
{
    const int is64 = detect_is64(mask);

    if (blockIdx.x >= nSpalBlocks) {
        // ---- mask tail: out[n_img + i] = (float)mask[i], 4 per thread ----
        const int tb = blockIdx.x - nSpalBlocks;
        const int q  = tb * blockDim.x + threadIdx.x;
        if (q < nq) {
            int m0, m1, m2, m3;
            load_mask_quad(mask, q, is64, m0, m1, m2, m3);
            float4 v = make_float4((float)m0, (float)m1, (float)m2, (float)m3);
            const long long n_img4 = (long long)KCH * CCH * nq;  // float4 units
            __stwt(&reinterpret_cast<float4*>(out)[n_img4 + q], v);
        }
        return;
    }

    // ---- spalize: 1 quad per thread, lanes contiguous ----
    const int qb = blockIdx.x % nblocksQ;
    const int ks = blockIdx.x / nblocksQ;
    const int q  = qb * blockDim.x + threadIdx.x;
    if (q >= nq) return;

    int m0, m1, m2, m3;
    load_mask_quad(mask, q, is64, m0, m1, m2, m3);

    const float4* img4 = reinterpret_cast<const float4*>(img);
    float4 ic0 = img4[0 * nq + q];
    float4 ic1 = img4[1 * nq + q];
    float4 ic2 = img4[2 * nq + q];

    float4* out4 = reinterpret_cast<float4*>(out);
    const int k0 = ks * KCHUNK;

    #pragma unroll
    for (int kk = 0; kk < KCHUNK; kk++) {
        const int k = k0 + kk;
        const long long obase = (long long)(k * CCH) * nq + q;
        __stwt(&out4[obase + 0LL * nq], sel4(ic0, m0, m1, m2, m3, k));
        __stwt(&out4[obase + 1LL * nq], sel4(ic1, m0, m1, m2, m3, k));
        __stwt(&out4[obase + 2LL * nq], sel4(ic2, m0, m1, m2, m3, k));
    }
}

extern "C" void kernel_launch(void* const* d_in, const int* in_sizes, int n_in,
                              void* d_out, int out_size)
{
    const float* img  = (const float*)d_in[0];
    const int*   mask = (const int*)d_in[1];
    float*       out  = (float*)d_out;

    const int HW = in_sizes[0] / CCH;       // 512*512
    const int nq = HW >> 2;                 // 65536

    const int threads     = 256;
    const int nblocksQ    = (nq + threads - 1) / threads;   // 256
    const int nSpalBlocks = nblocksQ * KSPLIT;              // 6400

    const long long n_img = (long long)KCH * CCH * HW;
    const bool wantTail = ((long long)out_size >= n_img + HW);
    const int grid = nSpalBlocks + (wantTail ? nblocksQ : 0);

    spalize_fused_kernel<<<grid, threads>>>(img, mask, out, nq, nblocksQ, nSpalBlocks);
}

// round 11
// speedup vs baseline: 1.2464x; 1.2464x over previous
#include <cuda_runtime.h>

// Spalize: out[k][c][h][w] = img[c][h][w] * (mask[h][w] == k), k in [0,50),
// plus the mask appended (as float) if out_size covers it.
//
// R9 store policy (.cs streaming) + 256-bit stores at FULL grid:
// 8 px/thread, KSPLIT=50 (KCHUNK=1) -> 6400 spalize blocks (~44/SM).
// st.global.cs.v8.b32 halves store instructions & L1 wavefront issue per
// byte vs float4 (L1 was the busiest unit at 67-72% in all prior runs).

#define KCH 50
#define CCH 3
#define KSPLIT 50
#define KCHUNK (KCH / KSPLIT)   // 1

__device__ __forceinline__ int detect_is64(const int* __restrict__ mask) {
    const int lane = threadIdx.x & 31;
    const int w1 = __ldg(&mask[2 * lane + 1]);
    const int w2 = __ldg(&mask[2 * (lane + 32) + 1]);
    const unsigned b = __ballot_sync(0xffffffffu, (w1 | w2) == 0);
    return b == 0xffffffffu;
}

// Load 8 mask labels for pixel block t (pixels t*8 .. t*8+7)
__device__ __forceinline__ void load_mask8(const int* __restrict__ mask,
                                           int t, int is64, int m[8]) {
    if (is64) {
        const int base = t * 16;  // 8 int64s; low word at even idx
        #pragma unroll
        for (int i = 0; i < 8; i++) m[i] = mask[base + 2 * i];
    } else {
        const int4 a = reinterpret_cast<const int4*>(mask)[2 * t];
        const int4 b = reinterpret_cast<const int4*>(mask)[2 * t + 1];
        m[0] = a.x; m[1] = a.y; m[2] = a.z; m[3] = a.w;
        m[4] = b.x; m[5] = b.y; m[6] = b.z; m[7] = b.w;
    }
}

__device__ __forceinline__ void st_cs_256(float* p, const float v[8]) {
    asm volatile(
        "st.global.cs.v8.b32 [%0], {%1,%2,%3,%4,%5,%6,%7,%8};"
        :: "l"(p),
           "r"(__float_as_uint(v[0])), "r"(__float_as_uint(v[1])),
           "r"(__float_as_uint(v[2])), "r"(__float_as_uint(v[3])),
           "r"(__float_as_uint(v[4])), "r"(__float_as_uint(v[5])),
           "r"(__float_as_uint(v[6])), "r"(__float_as_uint(v[7]))
        : "memory");
}

__global__ void __launch_bounds__(256) spalize_fused_kernel(
    const float* __restrict__ img,
    const int*   __restrict__ mask,
    float*       __restrict__ out,
    int nq8,           // HW/8
    int nblocksQ,      // nq8/256
    int nSpalBlocks)   // nblocksQ * KSPLIT
{
    const int is64 = detect_is64(mask);
    const int HW = nq8 * 8;

    if (blockIdx.x >= nSpalBlocks) {
        // ---- mask tail: out[n_img + i] = (float)mask[i], 8 per thread ----
        const int tb = blockIdx.x - nSpalBlocks;
        const int t  = tb * blockDim.x + threadIdx.x;
        if (t < nq8) {
            int m[8];
            load_mask8(mask, t, is64, m);
            float v[8];
            #pragma unroll
            for (int i = 0; i < 8; i++) v[i] = (float)m[i];
            const long long n_img = (long long)KCH * CCH * HW;
            st_cs_256(out + n_img + (long long)t * 8, v);
        }
        return;
    }

    // ---- spalize: 8 contiguous pixels per thread, KCHUNK=1 ----
    const int qb = blockIdx.x % nblocksQ;
    const int k  = blockIdx.x / nblocksQ;     // KCHUNK==1: chunk index == k
    const int t  = qb * blockDim.x + threadIdx.x;
    if (t >= nq8) return;

    int m[8];
    load_mask8(mask, t, is64, m);

    const float4* img4 = reinterpret_cast<const float4*>(img);
    const int nq4 = nq8 * 2;
    const long long tOff = (long long)t * 8;

    #pragma unroll
    for (int c = 0; c < CCH; c++) {
        float4 a = img4[c * nq4 + 2 * t];
        float4 b = img4[c * nq4 + 2 * t + 1];
        float v[8];
        v[0] = (m[0] == k) ? a.x : 0.0f;
        v[1] = (m[1] == k) ? a.y : 0.0f;
        v[2] = (m[2] == k) ? a.z : 0.0f;
        v[3] = (m[3] == k) ? a.w : 0.0f;
        v[4] = (m[4] == k) ? b.x : 0.0f;
        v[5] = (m[5] == k) ? b.y : 0.0f;
        v[6] = (m[6] == k) ? b.z : 0.0f;
        v[7] = (m[7] == k) ? b.w : 0.0f;
        st_cs_256(out + ((long long)(k * CCH + c) * HW + tOff), v);
    }
}

extern "C" void kernel_launch(void* const* d_in, const int* in_sizes, int n_in,
                              void* d_out, int out_size)
{
    const float* img  = (const float*)d_in[0];
    const int*   mask = (const int*)d_in[1];
    float*       out  = (float*)d_out;

    const int HW  = in_sizes[0] / CCH;      // 512*512
    const int nq8 = HW >> 3;                // 32768

    const int threads     = 256;
    const int nblocksQ    = (nq8 + threads - 1) / threads;  // 128
    const int nSpalBlocks = nblocksQ * KSPLIT;              // 6400

    const long long n_img = (long long)KCH * CCH * HW;
    const bool wantTail = ((long long)out_size >= n_img + HW);
    const int grid = nSpalBlocks + (wantTail ? nblocksQ : 0);

    spalize_fused_kernel<<<grid, threads>>>(img, mask, out, nq8, nblocksQ, nSpalBlocks);
}

// round 12
// speedup vs baseline: 1.5271x; 1.2252x over previous
#include <cuda_runtime.h>

// Spalize: out[k][c][h][w] = img[c][h][w] * (mask[h][w] == k), k in [0,50),
// plus the mask appended (as float) if out_size covers it.
//
// R9 base (.cs streaming float4 stores, fully coalesced) + delta:
// 2 quads per thread, WARP-STRIDED (qB = qA + blockDim) so each store
// instruction keeps contiguous lanes (unlike R3's contiguous-per-thread
// layout that split wavefronts). Halves loop overhead per byte, doubles
// per-thread store MLP. KSPLIT=25, grid 3328.

#define KCH 50
#define CCH 3
#define KSPLIT 25
#define KCHUNK (KCH / KSPLIT)   // 2

__device__ __forceinline__ int detect_is64(const int* __restrict__ mask) {
    const int lane = threadIdx.x & 31;
    const int w1 = __ldg(&mask[2 * lane + 1]);
    const int w2 = __ldg(&mask[2 * (lane + 32) + 1]);
    const unsigned b = __ballot_sync(0xffffffffu, (w1 | w2) == 0);
    return b == 0xffffffffu;
}

__device__ __forceinline__ void load_mask_quad(const int* __restrict__ mask,
                                               int q, int is64,
                                               int& m0, int& m1, int& m2, int& m3) {
    if (is64) {
        const int base = q * 8;   // 4 int64s; low word at even idx
        m0 = mask[base + 0]; m1 = mask[base + 2];
        m2 = mask[base + 4]; m3 = mask[base + 6];
    } else {
        const int4 mm = reinterpret_cast<const int4*>(mask)[q];
        m0 = mm.x; m1 = mm.y; m2 = mm.z; m3 = mm.w;
    }
}

__device__ __forceinline__ float4 sel4(float4 ic, int m0, int m1, int m2, int m3, int k) {
    float4 v;
    v.x = (m0 == k) ? ic.x : 0.0f;
    v.y = (m1 == k) ? ic.y : 0.0f;
    v.z = (m2 == k) ? ic.z : 0.0f;
    v.w = (m3 == k) ? ic.w : 0.0f;
    return v;
}

__global__ void __launch_bounds__(256) spalize_fused_kernel(
    const float* __restrict__ img,
    const int*   __restrict__ mask,
    float*       __restrict__ out,
    int nq,            // HW/4
    int nblocksQ,      // number of q-blocks, each covers 512 quads (strided)
    int nSpalBlocks)   // nblocksQ * KSPLIT
{
    const int is64 = detect_is64(mask);

    if (blockIdx.x >= nSpalBlocks) {
        // ---- mask tail: out[n_img + i] = (float)mask[i] ----
        const int tb = blockIdx.x - nSpalBlocks;
        const long long n_img4 = (long long)KCH * CCH * nq;  // float4 units
        #pragma unroll
        for (int j = 0; j < 2; j++) {
            const int q = (tb * 2 + j) * blockDim.x + threadIdx.x;
            if (q < nq) {
                int m0, m1, m2, m3;
                load_mask_quad(mask, q, is64, m0, m1, m2, m3);
                float4 v = make_float4((float)m0, (float)m1, (float)m2, (float)m3);
                __stcs(&reinterpret_cast<float4*>(out)[n_img4 + q], v);
            }
        }
        return;
    }

    // ---- spalize: 2 warp-strided quads per thread ----
    const int qb = blockIdx.x % nblocksQ;
    const int ks = blockIdx.x / nblocksQ;
    const int qA = qb * (blockDim.x * 2) + threadIdx.x;
    const int qB = qA + blockDim.x;
    if (qA >= nq) return;

    int a0, a1, a2, a3, b0, b1, b2, b3;
    load_mask_quad(mask, qA, is64, a0, a1, a2, a3);
    load_mask_quad(mask, qB, is64, b0, b1, b2, b3);

    const float4* img4 = reinterpret_cast<const float4*>(img);
    float4 iA0 = img4[0 * nq + qA], iB0 = img4[0 * nq + qB];
    float4 iA1 = img4[1 * nq + qA], iB1 = img4[1 * nq + qB];
    float4 iA2 = img4[2 * nq + qA], iB2 = img4[2 * nq + qB];

    float4* out4 = reinterpret_cast<float4*>(out);
    const int k0 = ks * KCHUNK;

    #pragma unroll
    for (int kk = 0; kk < KCHUNK; kk++) {
        const int k = k0 + kk;
        const long long obase = (long long)(k * CCH) * nq;
        __stcs(&out4[obase + 0LL * nq + qA], sel4(iA0, a0, a1, a2, a3, k));
        __stcs(&out4[obase + 0LL * nq + qB], sel4(iB0, b0, b1, b2, b3, k));
        __stcs(&out4[obase + 1LL * nq + qA], sel4(iA1, a0, a1, a2, a3, k));
        __stcs(&out4[obase + 1LL * nq + qB], sel4(iB1, b0, b1, b2, b3, k));
        __stcs(&out4[obase + 2LL * nq + qA], sel4(iA2, a0, a1, a2, a3, k));
        __stcs(&out4[obase + 2LL * nq + qB], sel4(iB2, b0, b1, b2, b3, k));
    }
}

extern "C" void kernel_launch(void* const* d_in, const int* in_sizes, int n_in,
                              void* d_out, int out_size)
{
    const float* img  = (const float*)d_in[0];
    const int*   mask = (const int*)d_in[1];
    float*       out  = (float*)d_out;

    const int HW = in_sizes[0] / CCH;       // 512*512
    const int nq = HW >> 2;                 // 65536

    const int threads     = 256;
    const int quadsPerBlk = threads * 2;                          // 512
    const int nblocksQ    = (nq + quadsPerBlk - 1) / quadsPerBlk; // 128
    const int nSpalBlocks = nblocksQ * KSPLIT;                    // 3200

    const long long n_img = (long long)KCH * CCH * HW;
    const bool wantTail = ((long long)out_size >= n_img + HW);
    const int grid = nSpalBlocks + (wantTail ? nblocksQ : 0);

    spalize_fused_kernel<<<grid, threads>>>(img, mask, out, nq, nblocksQ, nSpalBlocks);
}